// round 2
// baseline (speedup 1.0000x reference)
#include <cuda_runtime.h>

// NCC2D: local normalized cross-correlation, 9x9 box, zero pad, scalar -mean(cc)
// Inputs: y_true, y_pred : [32,1,512,512] fp32. Output: 1 fp32.
//
// cross = IJ_sum - I_sum*J_sum/81
// I_var = I2_sum - I_sum^2/81 ; J_var analogous
// cc    = cross^2 / (I_var*J_var + 1e-5) ; out = -mean(cc)

#define IMG_W 512
#define IMG_H 512
#define NBATCH 32
#define STRIP 32                    // output rows per warp-task
#define HALVES 2                    // 256-column halves
#define NTASK (NBATCH * (IMG_H / STRIP) * HALVES)   // 1024
#define WPB 4                       // warps per block
#define OUTC 8                      // output columns per lane
#define WINC 16                     // vertical-sum window columns per lane (OUTC + 8 halo)

__device__ float g_partials[NTASK];

// Load 16 consecutive floats at columns [cb, cb+16) of one image row, zero-filled
// outside [0, IMG_W). cb = c0-4 is a multiple of 4 -> 16B aligned when in range.
__device__ __forceinline__ void load_row16(const float* __restrict__ row, int cb,
                                           float (&v)[WINC]) {
    if (cb >= 0 && cb + WINC <= IMG_W) {
        const float4* p = reinterpret_cast<const float4*>(row + cb);
        float4 a = p[0], b = p[1], c = p[2], d = p[3];
        v[0] = a.x; v[1] = a.y; v[2] = a.z; v[3] = a.w;
        v[4] = b.x; v[5] = b.y; v[6] = b.z; v[7] = b.w;
        v[8] = c.x; v[9] = c.y; v[10] = c.z; v[11] = c.w;
        v[12] = d.x; v[13] = d.y; v[14] = d.z; v[15] = d.w;
    } else {
#pragma unroll
        for (int j = 0; j < WINC; j++) {
            int col = cb + j;
            v[j] = (col >= 0 && col < IMG_W) ? row[col] : 0.0f;
        }
    }
}

__global__ __launch_bounds__(WPB * 32)
void ncc_main(const float* __restrict__ gI, const float* __restrict__ gJ) {
    const int warp = blockIdx.x * WPB + (threadIdx.x >> 5);
    const int lane = threadIdx.x & 31;

    // task decode: warp -> (batch, strip, half)
    const int b     = warp >> 5;            // 32 tasks per batch
    const int strip = (warp >> 1) & 15;
    const int half  = warp & 1;
    const int r0 = strip * STRIP;
    const int c0 = half * 256 + lane * OUTC;
    const int cb = c0 - 4;                  // window start column

    const float* __restrict__ Ib = gI + (size_t)b * (IMG_H * IMG_W);
    const float* __restrict__ Jb = gJ + (size_t)b * (IMG_H * IMG_W);

    float vI[WINC], vJ[WINC], vI2[WINC], vJ2[WINC], vIJ[WINC];
#pragma unroll
    for (int j = 0; j < WINC; j++) { vI[j] = vJ[j] = vI2[j] = vJ2[j] = vIJ[j] = 0.0f; }

    // warm-up: accumulate rows [r0-4, r0+4)
    for (int rr = r0 - 4; rr < r0 + 4; rr++) {
        if (rr < 0) continue;
        float ti[WINC], tj[WINC];
        load_row16(Ib + rr * IMG_W, cb, ti);
        load_row16(Jb + rr * IMG_W, cb, tj);
#pragma unroll
        for (int j = 0; j < WINC; j++) {
            float a = ti[j], c = tj[j];
            vI[j] += a; vJ[j] += c;
            vI2[j] = fmaf(a, a, vI2[j]);
            vJ2[j] = fmaf(c, c, vJ2[j]);
            vIJ[j] = fmaf(a, c, vIJ[j]);
        }
    }

    const float s = 1.0f / 81.0f;
    // earliest row that was actually accumulated (bottom of the warm-up window)
    const int rlow = (r0 - 4 > 0) ? (r0 - 4) : 0;
    float acc = 0.0f;

    for (int r = r0; r < r0 + STRIP; r++) {
        const int rin = r + 4;
        if (rin < IMG_H) {
            float ti[WINC], tj[WINC];
            load_row16(Ib + rin * IMG_W, cb, ti);
            load_row16(Jb + rin * IMG_W, cb, tj);
#pragma unroll
            for (int j = 0; j < WINC; j++) {
                float a = ti[j], c = tj[j];
                vI[j] += a; vJ[j] += c;
                vI2[j] = fmaf(a, a, vI2[j]);
                vJ2[j] = fmaf(c, c, vJ2[j]);
                vIJ[j] = fmaf(a, c, vIJ[j]);
            }
        }
        // remove row r-5 ONLY if it was previously accumulated (>= rlow)
        const int rout = r - 5;
        if (rout >= rlow) {
            float ti[WINC], tj[WINC];
            load_row16(Ib + rout * IMG_W, cb, ti);
            load_row16(Jb + rout * IMG_W, cb, tj);
#pragma unroll
            for (int j = 0; j < WINC; j++) {
                float a = ti[j], c = tj[j];
                vI[j] -= a; vJ[j] -= c;
                vI2[j] = fmaf(-a, a, vI2[j]);
                vJ2[j] = fmaf(-c, c, vJ2[j]);
                vIJ[j] = fmaf(-a, c, vIJ[j]);
            }
        }

        // horizontal sliding 9-sum over the 16-wide window, fully in registers
        float hI  = vI[0] + vI[1] + vI[2] + vI[3] + vI[4] + vI[5] + vI[6] + vI[7] + vI[8];
        float hJ  = vJ[0] + vJ[1] + vJ[2] + vJ[3] + vJ[4] + vJ[5] + vJ[6] + vJ[7] + vJ[8];
        float hI2 = vI2[0]+vI2[1]+vI2[2]+vI2[3]+vI2[4]+vI2[5]+vI2[6]+vI2[7]+vI2[8];
        float hJ2 = vJ2[0]+vJ2[1]+vJ2[2]+vJ2[3]+vJ2[4]+vJ2[5]+vJ2[6]+vJ2[7]+vJ2[8];
        float hIJ = vIJ[0]+vIJ[1]+vIJ[2]+vIJ[3]+vIJ[4]+vIJ[5]+vIJ[6]+vIJ[7]+vIJ[8];

#pragma unroll
        for (int k = 0; k < OUTC; k++) {
            if (k > 0) {
                hI  += vI[k + 8]  - vI[k - 1];
                hJ  += vJ[k + 8]  - vJ[k - 1];
                hI2 += vI2[k + 8] - vI2[k - 1];
                hJ2 += vJ2[k + 8] - vJ2[k - 1];
                hIJ += vIJ[k + 8] - vIJ[k - 1];
            }
            float cross = fmaf(-hI * s, hJ, hIJ);
            float varI  = fmaf(-hI * s, hI, hI2);
            float varJ  = fmaf(-hJ * s, hJ, hJ2);
            float denom = fmaf(varI, varJ, 1e-5f);
            acc += __fdividef(cross * cross, denom);
        }
    }

    // deterministic warp reduction
#pragma unroll
    for (int o = 16; o > 0; o >>= 1)
        acc += __shfl_down_sync(0xffffffffu, acc, o);
    if (lane == 0)
        g_partials[warp] = acc;
}

__global__ void ncc_reduce(float* __restrict__ out) {
    __shared__ float sm[NTASK];
    const int t = threadIdx.x;
    sm[t] = g_partials[t];
    __syncthreads();
#pragma unroll
    for (int stride = NTASK / 2; stride > 0; stride >>= 1) {
        if (t < stride) sm[t] += sm[t + stride];
        __syncthreads();
    }
    if (t == 0)
        out[0] = -sm[0] * (1.0f / (float)(NBATCH * IMG_H * IMG_W));
}

extern "C" void kernel_launch(void* const* d_in, const int* in_sizes, int n_in,
                              void* d_out, int out_size) {
    const float* y_true = (const float*)d_in[0];
    const float* y_pred = (const float*)d_in[1];
    float* out = (float*)d_out;
    (void)in_sizes; (void)n_in; (void)out_size;

    ncc_main<<<NTASK / WPB, WPB * 32>>>(y_true, y_pred);
    ncc_reduce<<<1, NTASK>>>(out);
}

// round 3
// speedup vs baseline: 1.0823x; 1.0823x over previous
#include <cuda_runtime.h>

// NCC2D: local normalized cross-correlation, 9x9 box, zero pad, scalar -mean(cc)
// Inputs: y_true, y_pred : [32,1,512,512] fp32. Output: 1 fp32.
//
// cross = IJ_sum - I_sum*J_sum/81 ; I_var = I2_sum - I_sum^2/81 (ditto J)
// cc = cross^2 / (I_var*J_var + 1e-5) ; out = -mean(cc)

#define IMG_W 512
#define IMG_H 512
#define NBATCH 32
#define STRIP 16                    // output rows per warp-task
#define QUARTS 4                    // 128-column quarters
#define NSTRIPS (IMG_H / STRIP)     // 32
#define NTASK (NBATCH * NSTRIPS * QUARTS)   // 4096 warps
#define WPB 4                       // warps per block
#define NBLOCKS (NTASK / WPB)       // 1024
#define OUTC 4                      // output columns per lane
#define WINC 12                     // window columns per lane (OUTC + 8 halo)

__device__ float g_partials[NTASK];
__device__ unsigned int g_counter;   // zero-init at load; reset by last block

// Load 12 consecutive floats at columns [cb, cb+12), zero-filled outside
// [0, IMG_W). cb is a multiple of 4 -> 16B-aligned float4 on the fast path.
__device__ __forceinline__ void load_row12(const float* __restrict__ row, int cb,
                                           float (&v)[WINC]) {
    if (cb >= 0 && cb + WINC <= IMG_W) {
        const float4* p = reinterpret_cast<const float4*>(row + cb);
        float4 a = p[0], b = p[1], c = p[2];
        v[0] = a.x; v[1] = a.y; v[2]  = a.z; v[3]  = a.w;
        v[4] = b.x; v[5] = b.y; v[6]  = b.z; v[7]  = b.w;
        v[8] = c.x; v[9] = c.y; v[10] = c.z; v[11] = c.w;
    } else {
#pragma unroll
        for (int j = 0; j < WINC; j++) {
            int col = cb + j;
            v[j] = (col >= 0 && col < IMG_W) ? row[col] : 0.0f;
        }
    }
}

__global__ __launch_bounds__(WPB * 32)
void ncc_main(const float* __restrict__ gI, const float* __restrict__ gJ,
              float* __restrict__ out) {
    const int warp = blockIdx.x * WPB + (threadIdx.x >> 5);
    const int lane = threadIdx.x & 31;

    // task decode: warp -> (batch, strip, quarter)
    const int b     = warp >> 7;                 // 128 tasks per batch
    const int strip = (warp >> 2) & (NSTRIPS - 1);
    const int quart = warp & (QUARTS - 1);
    const int r0 = strip * STRIP;
    const int cb = quart * 128 + lane * OUTC - 4;   // window start column

    const float* __restrict__ Ib = gI + (size_t)b * (IMG_H * IMG_W);
    const float* __restrict__ Jb = gJ + (size_t)b * (IMG_H * IMG_W);

    float vI[WINC], vJ[WINC], vI2[WINC], vJ2[WINC], vIJ[WINC];
#pragma unroll
    for (int j = 0; j < WINC; j++) { vI[j] = vJ[j] = vI2[j] = vJ2[j] = vIJ[j] = 0.0f; }

    // warm-up: accumulate rows [r0-4, r0+4)
    for (int rr = (r0 - 4 < 0 ? 0 : r0 - 4); rr < r0 + 4; rr++) {
        float ti[WINC], tj[WINC];
        load_row12(Ib + rr * IMG_W, cb, ti);
        load_row12(Jb + rr * IMG_W, cb, tj);
#pragma unroll
        for (int j = 0; j < WINC; j++) {
            float a = ti[j], c = tj[j];
            vI[j] += a; vJ[j] += c;
            vI2[j] = fmaf(a, a, vI2[j]);
            vJ2[j] = fmaf(c, c, vJ2[j]);
            vIJ[j] = fmaf(a, c, vIJ[j]);
        }
    }

    const float s = 1.0f / 81.0f;
    const int rlow = (r0 - 4 > 0) ? (r0 - 4) : 0;  // earliest accumulated row
    float acc = 0.0f;

    for (int r = r0; r < r0 + STRIP; r++) {
        const int rin = r + 4;
        if (rin < IMG_H) {
            float ti[WINC], tj[WINC];
            load_row12(Ib + rin * IMG_W, cb, ti);
            load_row12(Jb + rin * IMG_W, cb, tj);
#pragma unroll
            for (int j = 0; j < WINC; j++) {
                float a = ti[j], c = tj[j];
                vI[j] += a; vJ[j] += c;
                vI2[j] = fmaf(a, a, vI2[j]);
                vJ2[j] = fmaf(c, c, vJ2[j]);
                vIJ[j] = fmaf(a, c, vIJ[j]);
            }
        }
        const int rout = r - 5;
        if (rout >= rlow) {   // remove only rows actually accumulated
            float ti[WINC], tj[WINC];
            load_row12(Ib + rout * IMG_W, cb, ti);
            load_row12(Jb + rout * IMG_W, cb, tj);
#pragma unroll
            for (int j = 0; j < WINC; j++) {
                float a = ti[j], c = tj[j];
                vI[j] -= a; vJ[j] -= c;
                vI2[j] = fmaf(-a, a, vI2[j]);
                vJ2[j] = fmaf(-c, c, vJ2[j]);
                vIJ[j] = fmaf(-a, c, vIJ[j]);
            }
        }

        // horizontal sliding 9-sum over the 12-wide window, in registers
        float hI  = vI[0]+vI[1]+vI[2]+vI[3]+vI[4]+vI[5]+vI[6]+vI[7]+vI[8];
        float hJ  = vJ[0]+vJ[1]+vJ[2]+vJ[3]+vJ[4]+vJ[5]+vJ[6]+vJ[7]+vJ[8];
        float hI2 = vI2[0]+vI2[1]+vI2[2]+vI2[3]+vI2[4]+vI2[5]+vI2[6]+vI2[7]+vI2[8];
        float hJ2 = vJ2[0]+vJ2[1]+vJ2[2]+vJ2[3]+vJ2[4]+vJ2[5]+vJ2[6]+vJ2[7]+vJ2[8];
        float hIJ = vIJ[0]+vIJ[1]+vIJ[2]+vIJ[3]+vIJ[4]+vIJ[5]+vIJ[6]+vIJ[7]+vIJ[8];

#pragma unroll
        for (int k = 0; k < OUTC; k++) {
            if (k > 0) {
                hI  += vI[k + 8]  - vI[k - 1];
                hJ  += vJ[k + 8]  - vJ[k - 1];
                hI2 += vI2[k + 8] - vI2[k - 1];
                hJ2 += vJ2[k + 8] - vJ2[k - 1];
                hIJ += vIJ[k + 8] - vIJ[k - 1];
            }
            float cross = fmaf(-hI * s, hJ, hIJ);
            float varI  = fmaf(-hI * s, hI, hI2);
            float varJ  = fmaf(-hJ * s, hJ, hJ2);
            float denom = fmaf(varI, varJ, 1e-5f);
            acc += __fdividef(cross * cross, denom);
        }
    }

    // deterministic warp reduction -> per-warp partial
#pragma unroll
    for (int o = 16; o > 0; o >>= 1)
        acc += __shfl_down_sync(0xffffffffu, acc, o);
    if (lane == 0)
        g_partials[warp] = acc;

    // ---- fused final reduction: last block to finish sums all partials ----
    __shared__ bool is_last;
    __shared__ float sm[WPB * 32];
    __syncthreads();                 // all 4 partials of this block are written
    if (threadIdx.x == 0) {
        __threadfence();             // publish partials before counting
        unsigned int done = atomicAdd(&g_counter, 1u);
        is_last = (done == (unsigned int)(NBLOCKS - 1));
    }
    __syncthreads();
    if (!is_last) return;

    __threadfence();                 // acquire: see all other blocks' partials
    // fixed-order sum: thread t sums indices t, t+128, ... (deterministic)
    float v = 0.0f;
    for (int i = threadIdx.x; i < NTASK; i += WPB * 32)
        v += g_partials[i];
    sm[threadIdx.x] = v;
    __syncthreads();
#pragma unroll
    for (int stride = WPB * 16; stride > 0; stride >>= 1) {
        if (threadIdx.x < stride) sm[threadIdx.x] += sm[threadIdx.x + stride];
        __syncthreads();
    }
    if (threadIdx.x == 0) {
        out[0] = -sm[0] * (1.0f / (float)(NBATCH * IMG_H * IMG_W));
        g_counter = 0;               // reset for next graph replay
    }
}

extern "C" void kernel_launch(void* const* d_in, const int* in_sizes, int n_in,
                              void* d_out, int out_size) {
    const float* y_true = (const float*)d_in[0];
    const float* y_pred = (const float*)d_in[1];
    float* out = (float*)d_out;
    (void)in_sizes; (void)n_in; (void)out_size;

    ncc_main<<<NBLOCKS, WPB * 32>>>(y_true, y_pred, out);
}

// round 4
// speedup vs baseline: 1.3651x; 1.2613x over previous
#include <cuda_runtime.h>

// NCC2D: local normalized cross-correlation, 9x9 box, zero pad, scalar -mean(cc)
// Inputs: y_true, y_pred : [32,1,512,512] fp32. Output: 1 fp32.
//
// cross = IJ_sum - I_sum*J_sum/81 ; I_var = I2_sum - I_sum^2/81 (ditto J)
// cc = cross^2 / (I_var*J_var + 1e-5) ; out = -mean(cc)
//
// One warp spans a full 512-wide row strip (16 cols/lane, no halo redundancy).
// Horizontal 9-window halos come from neighbor lanes via warp shuffle.

#define IMG_W 512
#define IMG_H 512
#define NBATCH 32
#define STRIP 8                      // output rows per warp-task
#define NSTRIPS (IMG_H / STRIP)      // 64
#define NTASK (NBATCH * NSTRIPS)     // 2048 warps
#define WPB 4
#define NBLOCKS (NTASK / WPB)        // 512
#define OUTC 16                      // columns per lane (32*16 = 512 = full row)

__device__ float g_partials[NTASK];
__device__ unsigned int g_counter;   // zero-init; reset by last block each run

// window accessor: i in [0,24) -> left halo (4) | own 16 | right halo (4)
#define WW(A, L, R, i) ((i) < 4 ? (L)[(i)] : ((i) < 20 ? (A)[(i)-4] : (R)[(i)-20]))

// accumulate (ADD) or remove (SUB) one image row into the vertical sums
template <bool ADD>
__device__ __forceinline__ void vrow(const float* __restrict__ Irow,
                                     const float* __restrict__ Jrow,
                                     float (&vI)[OUTC], float (&vJ)[OUTC],
                                     float (&vI2)[OUTC], float (&vJ2)[OUTC],
                                     float (&vIJ)[OUTC]) {
    const float4* pI = reinterpret_cast<const float4*>(Irow);
    const float4* pJ = reinterpret_cast<const float4*>(Jrow);
#pragma unroll
    for (int c = 0; c < 4; c++) {
        float4 a4 = pI[c];
        float4 c4 = pJ[c];
        float av[4] = {a4.x, a4.y, a4.z, a4.w};
        float cv[4] = {c4.x, c4.y, c4.z, c4.w};
#pragma unroll
        for (int q = 0; q < 4; q++) {
            int j = c * 4 + q;
            float a = av[q], ccv = cv[q];
            if (ADD) {
                vI[j] += a; vJ[j] += ccv;
                vI2[j] = fmaf(a, a, vI2[j]);
                vJ2[j] = fmaf(ccv, ccv, vJ2[j]);
                vIJ[j] = fmaf(a, ccv, vIJ[j]);
            } else {
                vI[j] -= a; vJ[j] -= ccv;
                vI2[j] = fmaf(-a, a, vI2[j]);
                vJ2[j] = fmaf(-ccv, ccv, vJ2[j]);
                vIJ[j] = fmaf(-a, ccv, vIJ[j]);
            }
        }
    }
}

__global__ __launch_bounds__(WPB * 32, 4)
void ncc_main(const float* __restrict__ gI, const float* __restrict__ gJ,
              float* __restrict__ out) {
    const int warp = blockIdx.x * WPB + (threadIdx.x >> 5);
    const int lane = threadIdx.x & 31;

    const int b     = warp >> 6;                 // 64 strips per batch
    const int strip = warp & (NSTRIPS - 1);
    const int r0 = strip * STRIP;
    const int col0 = lane * OUTC;                // always in [0, 512)

    const float* __restrict__ Ib = gI + (size_t)b * (IMG_H * IMG_W) + col0;
    const float* __restrict__ Jb = gJ + (size_t)b * (IMG_H * IMG_W) + col0;

    float vI[OUTC], vJ[OUTC], vI2[OUTC], vJ2[OUTC], vIJ[OUTC];
#pragma unroll
    for (int j = 0; j < OUTC; j++) { vI[j] = vJ[j] = vI2[j] = vJ2[j] = vIJ[j] = 0.0f; }

    // warm-up: rows [max(r0-4,0), r0+4)
    const int rlow = (r0 - 4 > 0) ? (r0 - 4) : 0;
    for (int rr = rlow; rr < r0 + 4; rr++)
        vrow<true>(Ib + rr * IMG_W, Jb + rr * IMG_W, vI, vJ, vI2, vJ2, vIJ);

    const float s = 1.0f / 81.0f;
    float acc = 0.0f;

    for (int r = r0; r < r0 + STRIP; r++) {
        const int rin = r + 4;
        if (rin < IMG_H)
            vrow<true>(Ib + rin * IMG_W, Jb + rin * IMG_W, vI, vJ, vI2, vJ2, vIJ);
        const int rout = r - 5;
        if (rout >= rlow)
            vrow<false>(Ib + rout * IMG_W, Jb + rout * IMG_W, vI, vJ, vI2, vJ2, vIJ);

        // halo vertical sums from neighbor lanes (image border -> 0)
        float LI[4], LJ[4], LI2[4], LJ2[4], LIJ[4];
        float RI[4], RJ[4], RI2[4], RJ2[4], RIJ[4];
#pragma unroll
        for (int q = 0; q < 4; q++) {
            LI[q]  = __shfl_up_sync(0xffffffffu, vI[12 + q], 1);
            LJ[q]  = __shfl_up_sync(0xffffffffu, vJ[12 + q], 1);
            LI2[q] = __shfl_up_sync(0xffffffffu, vI2[12 + q], 1);
            LJ2[q] = __shfl_up_sync(0xffffffffu, vJ2[12 + q], 1);
            LIJ[q] = __shfl_up_sync(0xffffffffu, vIJ[12 + q], 1);
            RI[q]  = __shfl_down_sync(0xffffffffu, vI[q], 1);
            RJ[q]  = __shfl_down_sync(0xffffffffu, vJ[q], 1);
            RI2[q] = __shfl_down_sync(0xffffffffu, vI2[q], 1);
            RJ2[q] = __shfl_down_sync(0xffffffffu, vJ2[q], 1);
            RIJ[q] = __shfl_down_sync(0xffffffffu, vIJ[q], 1);
            if (lane == 0)  { LI[q] = LJ[q] = LI2[q] = LJ2[q] = LIJ[q] = 0.0f; }
            if (lane == 31) { RI[q] = RJ[q] = RI2[q] = RJ2[q] = RIJ[q] = 0.0f; }
        }

        // horizontal sliding 9-sum over the 24-wide (halo|own|halo) window
        float hI = 0, hJ = 0, hI2 = 0, hJ2 = 0, hIJ = 0;
#pragma unroll
        for (int i = 0; i < 9; i++) {
            hI  += WW(vI,  LI,  RI,  i);
            hJ  += WW(vJ,  LJ,  RJ,  i);
            hI2 += WW(vI2, LI2, RI2, i);
            hJ2 += WW(vJ2, LJ2, RJ2, i);
            hIJ += WW(vIJ, LIJ, RIJ, i);
        }

#pragma unroll
        for (int k = 0; k < OUTC; k++) {
            if (k > 0) {
                hI  += WW(vI,  LI,  RI,  k + 8) - WW(vI,  LI,  RI,  k - 1);
                hJ  += WW(vJ,  LJ,  RJ,  k + 8) - WW(vJ,  LJ,  RJ,  k - 1);
                hI2 += WW(vI2, LI2, RI2, k + 8) - WW(vI2, LI2, RI2, k - 1);
                hJ2 += WW(vJ2, LJ2, RJ2, k + 8) - WW(vJ2, LJ2, RJ2, k - 1);
                hIJ += WW(vIJ, LIJ, RIJ, k + 8) - WW(vIJ, LIJ, RIJ, k - 1);
            }
            float t = hI * s;
            float u = hJ * s;
            float cross = fmaf(-t, hJ, hIJ);
            float varI  = fmaf(-t, hI, hI2);
            float varJ  = fmaf(-u, hJ, hJ2);
            float denom = fmaf(varI, varJ, 1e-5f);
            acc += __fdividef(cross * cross, denom);
        }
    }

    // deterministic warp reduction -> per-warp partial
#pragma unroll
    for (int o = 16; o > 0; o >>= 1)
        acc += __shfl_down_sync(0xffffffffu, acc, o);
    if (lane == 0)
        g_partials[warp] = acc;

    // fused final reduction: last finishing block sums all partials
    __shared__ bool is_last;
    __shared__ float sm[WPB * 32];
    __syncthreads();
    if (threadIdx.x == 0) {
        __threadfence();
        unsigned int done = atomicAdd(&g_counter, 1u);
        is_last = (done == (unsigned int)(NBLOCKS - 1));
    }
    __syncthreads();
    if (!is_last) return;

    __threadfence();
    float v = 0.0f;
    for (int i = threadIdx.x; i < NTASK; i += WPB * 32)
        v += g_partials[i];
    sm[threadIdx.x] = v;
    __syncthreads();
#pragma unroll
    for (int stride = WPB * 16; stride > 0; stride >>= 1) {
        if (threadIdx.x < stride) sm[threadIdx.x] += sm[threadIdx.x + stride];
        __syncthreads();
    }
    if (threadIdx.x == 0) {
        out[0] = -sm[0] * (1.0f / (float)(NBATCH * IMG_H * IMG_W));
        g_counter = 0;
    }
}

extern "C" void kernel_launch(void* const* d_in, const int* in_sizes, int n_in,
                              void* d_out, int out_size) {
    const float* y_true = (const float*)d_in[0];
    const float* y_pred = (const float*)d_in[1];
    float* out = (float*)d_out;
    (void)in_sizes; (void)n_in; (void)out_size;

    ncc_main<<<NBLOCKS, WPB * 32>>>(y_true, y_pred, out);
}